// round 2
// baseline (speedup 1.0000x reference)
#include <cuda_runtime.h>

// Problem constants
#define NN   128   // MSA depth
#define LL   256   // sequence length
#define CM   256   // c_m
#define CH   32    // c_h
#define CZ   128   // c_z

// Scratch: a,b projections laid out [n][i*CH + c]  (K-major for stage-1 GEMM)
__device__ float g_A[NN * LL * CH];   // 4 MB
__device__ float g_B[NN * LL * CH];   // 4 MB

// ---------------------------------------------------------------------------
// Block reduce over 256 threads
// ---------------------------------------------------------------------------
__device__ __forceinline__ float block_reduce_256(float v, float* scratch) {
#pragma unroll
    for (int o = 16; o > 0; o >>= 1) v += __shfl_xor_sync(0xffffffffu, v, o);
    if ((threadIdx.x & 31) == 0) scratch[threadIdx.x >> 5] = v;
    __syncthreads();
    if (threadIdx.x < 32) {
        float t = (threadIdx.x < 8) ? scratch[threadIdx.x] : 0.f;
#pragma unroll
        for (int o = 4; o > 0; o >>= 1) t += __shfl_xor_sync(0xffffffffu, t, o);
        if (threadIdx.x == 0) scratch[0] = t;
    }
    __syncthreads();
    float r = scratch[0];
    __syncthreads();   // protect scratch before next use
    return r;
}

// ---------------------------------------------------------------------------
// Kernel 1: LayerNorm + projections a = (LN(m)@Wa+ba)*mask, b likewise.
// One block (256 thr) handles 32 rows of (n,i). Wa/Wb cached in SMEM.
// ---------------------------------------------------------------------------
__global__ __launch_bounds__(256) void ln_proj_kernel(
    const float* __restrict__ m, const float* __restrict__ mask,
    const float* __restrict__ gamma, const float* __restrict__ beta,
    const float* __restrict__ Wa, const float* __restrict__ ba,
    const float* __restrict__ Wb, const float* __restrict__ bb)
{
    extern __shared__ float sm1[];
    float* sWa     = sm1;            // 8192
    float* sWb     = sWa + 8192;     // 8192
    float* xs      = sWb + 8192;     // 256
    float* sred    = xs + 256;       // 256
    float* scratch = sred + 256;     // 32

    const int tid = threadIdx.x;
    for (int l = tid; l < 8192; l += 256) { sWa[l] = Wa[l]; sWb[l] = Wb[l]; }
    __syncthreads();

    const float gam = gamma[tid];
    const float bet = beta[tid];

    // projection mapping: out = tid&63 (0..31 -> a, 32..63 -> b), part = tid>>6
    const int out  = tid & 63;
    const int part = tid >> 6;
    const int h    = out & 31;
    const float* W = (out < 32) ? sWa : sWb;

    for (int rr = 0; rr < 32; rr++) {
        const int row = blockIdx.x * 32 + rr;           // row = n*LL + i
        const float xv = m[row * CM + tid];
        const float mean = block_reduce_256(xv, scratch) * (1.f / 256.f);
        const float d = xv - mean;
        const float var = block_reduce_256(d * d, scratch) * (1.f / 256.f);
        xs[tid] = d * rsqrtf(var + 1e-5f) * gam + bet;
        __syncthreads();

        float s = 0.f;
#pragma unroll
        for (int kk = 0; kk < 64; kk++) {
            const int k = part * 64 + kk;
            s += xs[k] * W[k * 32 + h];
        }
        sred[tid] = s;   // tid = part*64 + out
        __syncthreads();

        if (tid < 64) {
            float tot = sred[tid] + sred[tid + 64] + sred[tid + 128] + sred[tid + 192];
            const float mk = mask[row];
            const int n = row >> 8;
            const int i = row & 255;
            if (tid < 32) g_A[(n * LL + i) * CH + h] = (tot + ba[h]) * mk;
            else          g_B[(n * LL + i) * CH + h] = (tot + bb[h]) * mk;
        }
        __syncthreads();
    }
}

// ---------------------------------------------------------------------------
// Kernel 2: fused outer-product GEMM (A^T B tile, K = N = 128) + Wo contraction.
// Each CTA: 4 i's x 4 j's -> O tile [128,128] -> 16 pairs x 128 z outputs.
// 512 threads. Stage 1: classic register-tiled GEMM (4x8 per thread, strided
// mapping for conflict-free LDS). Stage 2: warp = pair, lane owns 4 z's
// (float4 loads of Wo staged through SMEM in 32-cd-row chunks).
// ---------------------------------------------------------------------------
__global__ __launch_bounds__(512) void fused_opm_kernel(
    const float* __restrict__ mask,
    const float* __restrict__ Wo, const float* __restrict__ bo,
    float* __restrict__ out)
{
    extern __shared__ float sm2[];
    float* As = sm2;            // [16][128]
    float* Bs = sm2 + 2048;     // [16][128]

    const int tid = threadIdx.x;
    const int i0 = blockIdx.y * 4;
    const int j0 = blockIdx.x * 4;
    const int ty = tid >> 4;    // 0..31
    const int tx = tid & 15;    // 0..15

    float acc[4][8];
#pragma unroll
    for (int u = 0; u < 4; u++)
#pragma unroll
        for (int v = 0; v < 8; v++) acc[u][v] = 0.f;

    // ---- Stage 1: O[r][s] = sum_n A[n][i0*32+r] * B[n][j0*32+s] ----
    for (int k0 = 0; k0 < 128; k0 += 16) {
        for (int l = tid; l < 2048; l += 512) {
            const int kk = l >> 7, r = l & 127;
            As[l] = g_A[(k0 + kk) * (LL * CH) + i0 * CH + r];
            Bs[l] = g_B[(k0 + kk) * (LL * CH) + j0 * CH + r];
        }
        __syncthreads();
#pragma unroll
        for (int kk = 0; kk < 16; kk++) {
            float af[4], bf[8];
#pragma unroll
            for (int u = 0; u < 4; u++) af[u] = As[kk * 128 + ty + 32 * u];
#pragma unroll
            for (int v = 0; v < 8; v++) bf[v] = Bs[kk * 128 + tx + 16 * v];
#pragma unroll
            for (int u = 0; u < 4; u++)
#pragma unroll
                for (int v = 0; v < 8; v++) acc[u][v] += af[u] * bf[v];
        }
        __syncthreads();
    }

    // ---- Spill O tile to SMEM ----
    float* O    = sm2;                    // [128][128]
    float* Wos  = sm2 + 16384;            // [32][128]
    float* pmsh = sm2 + 16384 + 4096;     // [16]
#pragma unroll
    for (int u = 0; u < 4; u++)
#pragma unroll
        for (int v = 0; v < 8; v++)
            O[(ty + 32 * u) * 128 + tx + 16 * v] = acc[u][v];

    if (tid < 16) {
        const int ii = i0 + (tid >> 2), jj = j0 + (tid & 3);
        float s = 0.f;
        for (int n = 0; n < NN; n++) s += mask[n * LL + ii] * mask[n * LL + jj];
        pmsh[tid] = s;
    }

    // ---- Stage 2: z[pair][z] = sum_cd O[pair(cd)] * Wo[cd][z] ----
    const int w    = tid >> 5;            // warp = pair 0..15
    const int lane = tid & 31;
    const int ii = w >> 2, jj = w & 3;
    float z0 = 0.f, z1 = 0.f, z2 = 0.f, z3 = 0.f;

    for (int cc = 0; cc < 1024; cc += 32) {     // chunk = one c value (32 d's)
        __syncthreads();                         // also covers O/pmsh writes on 1st iter
        for (int l = tid; l < 4096; l += 512) Wos[l] = Wo[cc * 128 + l];
        __syncthreads();
        const float* Orow = O + (ii * 32 + (cc >> 5)) * 128 + jj * 32;
#pragma unroll
        for (int r = 0; r < 32; r++) {
            const float ov = Orow[r];                       // broadcast
            const float4 wv = reinterpret_cast<const float4*>(Wos + r * 128)[lane];
            z0 += ov * wv.x; z1 += ov * wv.y; z2 += ov * wv.z; z3 += ov * wv.w;
        }
    }

    const float inv = 1.f / (pmsh[w] + 1e-8f);
    const float4 bv = reinterpret_cast<const float4*>(bo)[lane];
    float4 res;
    res.x = z0 * inv + bv.x;
    res.y = z1 * inv + bv.y;
    res.z = z2 * inv + bv.z;
    res.w = z3 * inv + bv.w;
    reinterpret_cast<float4*>(out)[((i0 + ii) * LL + (j0 + jj)) * 32 + lane] = res;
}

// ---------------------------------------------------------------------------
extern "C" void kernel_launch(void* const* d_in, const int* in_sizes, int n_in,
                              void* d_out, int out_size)
{
    const float* m     = (const float*)d_in[0];
    const float* mask  = (const float*)d_in[1];
    const float* gamma = (const float*)d_in[2];
    const float* beta  = (const float*)d_in[3];
    const float* Wa    = (const float*)d_in[4];
    const float* ba    = (const float*)d_in[5];
    const float* Wb    = (const float*)d_in[6];
    const float* bb    = (const float*)d_in[7];
    const float* Wo    = (const float*)d_in[8];
    const float* bo    = (const float*)d_in[9];
    float* out = (float*)d_out;

    const int smem1 = (8192 + 8192 + 256 + 256 + 32) * (int)sizeof(float);   // ~66 KB
    const int smem2 = (16384 + 4096 + 16) * (int)sizeof(float);              // ~80 KB
    cudaFuncSetAttribute(ln_proj_kernel,  cudaFuncAttributeMaxDynamicSharedMemorySize, smem1);
    cudaFuncSetAttribute(fused_opm_kernel, cudaFuncAttributeMaxDynamicSharedMemorySize, smem2);

    ln_proj_kernel<<<(NN * LL) / 32, 256, smem1>>>(m, mask, gamma, beta, Wa, ba, Wb, bb);

    dim3 grid(LL / 4, LL / 4);   // 64 x 64
    fused_opm_kernel<<<grid, 512, smem2>>>(mask, Wo, bo, out);
}

// round 3
// speedup vs baseline: 1.3691x; 1.3691x over previous
#include <cuda_runtime.h>

#define NN   128
#define LL   256
#define CM   256
#define CH   32
#define CZ   128

// a,b projections laid out [n][i*CH + c]  (K-major for stage-1 GEMM)
__device__ float g_A[NN * LL * CH];   // 4 MB
__device__ float g_B[NN * LL * CH];   // 4 MB

// ---------------------------------------------------------------------------
__device__ __forceinline__ float block_reduce_256(float v, float* scratch) {
#pragma unroll
    for (int o = 16; o > 0; o >>= 1) v += __shfl_xor_sync(0xffffffffu, v, o);
    if ((threadIdx.x & 31) == 0) scratch[threadIdx.x >> 5] = v;
    __syncthreads();
    if (threadIdx.x < 32) {
        float t = (threadIdx.x < 8) ? scratch[threadIdx.x] : 0.f;
#pragma unroll
        for (int o = 4; o > 0; o >>= 1) t += __shfl_xor_sync(0xffffffffu, t, o);
        if (threadIdx.x == 0) scratch[0] = t;
    }
    __syncthreads();
    float r = scratch[0];
    __syncthreads();
    return r;
}

// ---------------------------------------------------------------------------
// Kernel 1: LayerNorm + projections (unchanged from passing R1 kernel)
// ---------------------------------------------------------------------------
__global__ __launch_bounds__(256) void ln_proj_kernel(
    const float* __restrict__ m, const float* __restrict__ mask,
    const float* __restrict__ gamma, const float* __restrict__ beta,
    const float* __restrict__ Wa, const float* __restrict__ ba,
    const float* __restrict__ Wb, const float* __restrict__ bb)
{
    extern __shared__ float sm1[];
    float* sWa     = sm1;
    float* sWb     = sWa + 8192;
    float* xs      = sWb + 8192;
    float* sred    = xs + 256;
    float* scratch = sred + 256;

    const int tid = threadIdx.x;
    for (int l = tid; l < 8192; l += 256) { sWa[l] = Wa[l]; sWb[l] = Wb[l]; }
    __syncthreads();

    const float gam = gamma[tid];
    const float bet = beta[tid];

    const int out  = tid & 63;
    const int part = tid >> 6;
    const int h    = out & 31;
    const float* W = (out < 32) ? sWa : sWb;

    for (int rr = 0; rr < 32; rr++) {
        const int row = blockIdx.x * 32 + rr;
        const float xv = m[row * CM + tid];
        const float mean = block_reduce_256(xv, scratch) * (1.f / 256.f);
        const float d = xv - mean;
        const float var = block_reduce_256(d * d, scratch) * (1.f / 256.f);
        xs[tid] = d * rsqrtf(var + 1e-5f) * gam + bet;
        __syncthreads();

        float s = 0.f;
#pragma unroll
        for (int kk = 0; kk < 64; kk++) {
            const int k = part * 64 + kk;
            s += xs[k] * W[k * 32 + h];
        }
        sred[tid] = s;
        __syncthreads();

        if (tid < 64) {
            float tot = sred[tid] + sred[tid + 64] + sred[tid + 128] + sred[tid + 192];
            const float mk = mask[row];
            const int n = row >> 8;
            const int i = row & 255;
            if (tid < 32) g_A[(n * LL + i) * CH + h] = (tot + ba[h]) * mk;
            else          g_B[(n * LL + i) * CH + h] = (tot + bb[h]) * mk;
        }
        __syncthreads();
    }
}

// ---------------------------------------------------------------------------
// Kernel 2: fused O = A^T B tile (128x128, K=128) + Wo contraction.
// 512 threads, tile = 4 i x 4 j. All SMEM reads vectorized / broadcast.
//
// SMEM (floats):
//   stage 1:  As[32*128]=0..4095, Bs[32*128]=4096..8191
//   stage 2:  O[128*128]=0..16383, W2[64*128]=16384..24575 (reused as partials)
//   pmsh[16] at 24576
// ---------------------------------------------------------------------------
__global__ __launch_bounds__(512, 2) void fused_opm_kernel(
    const float* __restrict__ mask,
    const float* __restrict__ Wo, const float* __restrict__ bo,
    float* __restrict__ out)
{
    extern __shared__ float sm2[];
    float* As   = sm2;
    float* Bs   = sm2 + 4096;
    float* O    = sm2;
    float* W2   = sm2 + 16384;
    float* pmsh = sm2 + 24576;

    const int tid  = threadIdx.x;
    const int lane = tid & 31;
    const int w    = tid >> 5;          // 16 warps
    const int i0   = blockIdx.y * 4;
    const int j0   = blockIdx.x * 4;

    // ---- pair mask: warp w handles pair p=w = ii*4+jj ----
    {
        const int ii = i0 + (w >> 2), jj = j0 + (w & 3);
        float s = 0.f;
#pragma unroll
        for (int n = lane; n < NN; n += 32) s += mask[n * LL + ii] * mask[n * LL + jj];
#pragma unroll
        for (int o = 16; o > 0; o >>= 1) s += __shfl_xor_sync(0xffffffffu, s, o);
        if (lane == 0) pmsh[w] = s;
    }

    // ---- Stage 1: O[r][s] = sum_n A[n][i0*32+r] * B[n][j0*32+s] ----
    const int ty = tid >> 4;            // 0..31 -> rows ty*4..ty*4+3
    const int tx = tid & 15;            // 0..15 -> cols tx*8..tx*8+7

    float acc[4][8];
#pragma unroll
    for (int u = 0; u < 4; u++)
#pragma unroll
        for (int v = 0; v < 8; v++) acc[u][v] = 0.f;

    for (int k0 = 0; k0 < 128; k0 += 32) {
        __syncthreads();
#pragma unroll
        for (int l = tid * 4; l < 4096; l += 2048) {
            const int kk = l >> 7, r = l & 127;
            *reinterpret_cast<float4*>(As + l) =
                *reinterpret_cast<const float4*>(g_A + (k0 + kk) * (LL * CH) + i0 * CH + r);
            *reinterpret_cast<float4*>(Bs + l) =
                *reinterpret_cast<const float4*>(g_B + (k0 + kk) * (LL * CH) + j0 * CH + r);
        }
        __syncthreads();
#pragma unroll 8
        for (int kk = 0; kk < 32; kk++) {
            const float4 a4 = *reinterpret_cast<const float4*>(As + kk * 128 + ty * 4);
            const float4 b0 = *reinterpret_cast<const float4*>(Bs + kk * 128 + tx * 8);
            const float4 b1 = *reinterpret_cast<const float4*>(Bs + kk * 128 + tx * 8 + 4);
            const float af[4] = {a4.x, a4.y, a4.z, a4.w};
            const float bf[8] = {b0.x, b0.y, b0.z, b0.w, b1.x, b1.y, b1.z, b1.w};
#pragma unroll
            for (int u = 0; u < 4; u++)
#pragma unroll
                for (int v = 0; v < 8; v++) acc[u][v] += af[u] * bf[v];
        }
    }

    // ---- Spill O tile (float4 stores) ----
    __syncthreads();
#pragma unroll
    for (int u = 0; u < 4; u++) {
        *reinterpret_cast<float4*>(O + (ty * 4 + u) * 128 + tx * 8) =
            make_float4(acc[u][0], acc[u][1], acc[u][2], acc[u][3]);
        *reinterpret_cast<float4*>(O + (ty * 4 + u) * 128 + tx * 8 + 4) =
            make_float4(acc[u][4], acc[u][5], acc[u][6], acc[u][7]);
    }

    // ---- Stage 2: z[p][z] = sum_k O_p[k] * Wo[k][z]  (M=16,N=128,K=1024) ----
    // warp w: pb = w&3 (j_loc), kc = w>>2 (K-split of 4). lane owns z = lane*4..+3.
    // thread accumulates 4 i_loc x 4 z.
    const int pb = w & 3;
    const int kc = w >> 2;

    float4 zacc[4];
#pragma unroll
    for (int il = 0; il < 4; il++) zacc[il] = make_float4(0.f, 0.f, 0.f, 0.f);

    for (int st = 0; st < 16; st++) {            // Wo rows [st*64, st*64+64)
        __syncthreads();
#pragma unroll
        for (int l = tid * 4; l < 8192; l += 2048)
            *reinterpret_cast<float4*>(W2 + l) =
                *reinterpret_cast<const float4*>(Wo + st * 8192 + l);
        __syncthreads();

#pragma unroll
        for (int t = 0; t < 16; t++) {
            const int kr = kc + 4 * t;           // row within staged chunk, 0..63
            const int k  = st * 64 + kr;         // global k = c*32+d
            const int c  = k >> 5;
            const int d  = k & 31;
            const float4 wv = *reinterpret_cast<const float4*>(W2 + kr * 128 + lane * 4);
            const float* op = O + c * 128 + pb * 32 + d;
#pragma unroll
            for (int il = 0; il < 4; il++) {
                const float ov = op[il * 4096];  // broadcast
                zacc[il].x += ov * wv.x;
                zacc[il].y += ov * wv.y;
                zacc[il].z += ov * wv.z;
                zacc[il].w += ov * wv.w;
            }
        }
    }

    // ---- K-split reduction through W2 region ----
    __syncthreads();
#pragma unroll
    for (int il = 0; il < 4; il++)
        *reinterpret_cast<float4*>(W2 + (kc * 16 + il * 4 + pb) * 128 + lane * 4) = zacc[il];
    __syncthreads();

    // warp w = pair p; lane -> 4 z's
    float4 r0 = *reinterpret_cast<const float4*>(W2 + (0 * 16 + w) * 128 + lane * 4);
    float4 r1 = *reinterpret_cast<const float4*>(W2 + (1 * 16 + w) * 128 + lane * 4);
    float4 r2 = *reinterpret_cast<const float4*>(W2 + (2 * 16 + w) * 128 + lane * 4);
    float4 r3 = *reinterpret_cast<const float4*>(W2 + (3 * 16 + w) * 128 + lane * 4);

    const float inv = 1.f / (pmsh[w] + 1e-8f);
    const float4 bv = *reinterpret_cast<const float4*>(bo + lane * 4);
    float4 res;
    res.x = (r0.x + r1.x + r2.x + r3.x) * inv + bv.x;
    res.y = (r0.y + r1.y + r2.y + r3.y) * inv + bv.y;
    res.z = (r0.z + r1.z + r2.z + r3.z) * inv + bv.z;
    res.w = (r0.w + r1.w + r2.w + r3.w) * inv + bv.w;

    const int ii = i0 + (w >> 2), jj = j0 + (w & 3);
    *reinterpret_cast<float4*>(out + (ii * LL + jj) * CZ + lane * 4) = res;
}

// ---------------------------------------------------------------------------
extern "C" void kernel_launch(void* const* d_in, const int* in_sizes, int n_in,
                              void* d_out, int out_size)
{
    const float* m     = (const float*)d_in[0];
    const float* mask  = (const float*)d_in[1];
    const float* gamma = (const float*)d_in[2];
    const float* beta  = (const float*)d_in[3];
    const float* Wa    = (const float*)d_in[4];
    const float* ba    = (const float*)d_in[5];
    const float* Wb    = (const float*)d_in[6];
    const float* bb    = (const float*)d_in[7];
    const float* Wo    = (const float*)d_in[8];
    const float* bo    = (const float*)d_in[9];
    float* out = (float*)d_out;

    const int smem1 = (8192 + 8192 + 256 + 256 + 32) * (int)sizeof(float);
    const int smem2 = (24576 + 16) * (int)sizeof(float);    // ~96.1 KB
    cudaFuncSetAttribute(ln_proj_kernel,   cudaFuncAttributeMaxDynamicSharedMemorySize, smem1);
    cudaFuncSetAttribute(fused_opm_kernel, cudaFuncAttributeMaxDynamicSharedMemorySize, smem2);

    ln_proj_kernel<<<(NN * LL) / 32, 256, smem1>>>(m, mask, gamma, beta, Wa, ba, Wb, bb);

    dim3 grid(LL / 4, LL / 4);
    fused_opm_kernel<<<grid, 512, smem2>>>(mask, Wo, bo, out);
}

// round 5
// speedup vs baseline: 3.0109x; 2.1992x over previous
#include <cuda_runtime.h>
#include <cuda_bf16.h>
#include <cstdint>

#define NN 128
#define LL 256
#define CM 256
#define CH 32
#define CZ 128
#define RTOT 8192   // LL*CH

// ---------------- global scratch ----------------
__device__ __align__(16) __nv_bfloat16 g_Ah[RTOT * NN];   // [r][n] K-major, ld=128
__device__ __align__(16) __nv_bfloat16 g_Al[RTOT * NN];
__device__ __align__(16) __nv_bfloat16 g_Bh[RTOT * NN];
__device__ __align__(16) __nv_bfloat16 g_Bl[RTOT * NN];
__device__ __align__(16) __nv_bfloat16 g_Woh[CZ * 1024];  // [z][k], ld=1024 (Wo^T)
__device__ __align__(16) __nv_bfloat16 g_Wol[CZ * 1024];
__device__ float g_pm[LL * LL];
__device__ float g_O[(size_t)RTOT * RTOT];                // 256 MB

// ---------------- helpers ----------------
__device__ __forceinline__ uint32_t smem_u32(const void* p) {
    uint32_t a;
    asm("{ .reg .u64 t; cvta.to.shared.u64 t, %1; cvt.u32.u64 %0, t; }" : "=r"(a) : "l"(p));
    return a;
}

__device__ __forceinline__ void ldsm4(uint32_t* r, uint32_t addr) {
    asm volatile("ldmatrix.sync.aligned.m8n8.x4.shared.b16 {%0,%1,%2,%3}, [%4];"
        : "=r"(r[0]), "=r"(r[1]), "=r"(r[2]), "=r"(r[3]) : "r"(addr));
}

__device__ __forceinline__ void mma_bf16(float* d, const uint32_t* a,
                                         uint32_t b0, uint32_t b1) {
    asm volatile(
        "mma.sync.aligned.m16n8k16.row.col.f32.bf16.bf16.f32 "
        "{%0,%1,%2,%3}, {%4,%5,%6,%7}, {%8,%9}, {%0,%1,%2,%3};"
        : "+f"(d[0]), "+f"(d[1]), "+f"(d[2]), "+f"(d[3])
        : "r"(a[0]), "r"(a[1]), "r"(a[2]), "r"(a[3]), "r"(b0), "r"(b1));
}

__device__ __forceinline__ void split1(float x, __nv_bfloat16& h, __nv_bfloat16& l) {
    h = __float2bfloat16(x);
    l = __float2bfloat16(x - __bfloat162float(h));
}

// ---------------------------------------------------------------------------
// Kernel 1: LayerNorm + projections -> bf16 hi/lo, layout [i*32+h][n]
// ---------------------------------------------------------------------------
__global__ __launch_bounds__(256) void ln_proj_kernel(
    const float* __restrict__ m, const float* __restrict__ mask,
    const float* __restrict__ gamma, const float* __restrict__ beta,
    const float* __restrict__ Wa, const float* __restrict__ ba,
    const float* __restrict__ Wb, const float* __restrict__ bb)
{
    extern __shared__ float sm1[];
    float* sWa  = sm1;
    float* sWb  = sWa + 8192;
    float* xs   = sWb + 8192;
    float* sred = xs + 256;
    float* scr  = sred + 256;
    __nv_bfloat16* sStage = (__nv_bfloat16*)(scr + 16);   // 4 * 1024 bf16

    const int tid = threadIdx.x;
    for (int l = tid; l < 8192; l += 256) { sWa[l] = Wa[l]; sWb[l] = Wb[l]; }
    __syncthreads();

    const float gam = gamma[tid];
    const float bet = beta[tid];

    const int outp = tid & 63;
    const int part = tid >> 6;
    const int h    = outp & 31;
    const float* W = (outp < 32) ? sWa : sWb;

    const int nb = blockIdx.x >> 7;
    const int ib = blockIdx.x & 127;
    const int n0 = nb * 16;
    const int i0 = ib * 2;

    for (int rr = 0; rr < 32; rr++) {
        const int n_loc = rr & 15;
        const int i_loc = rr >> 4;
        const int row = (n0 + n_loc) * LL + (i0 + i_loc);

        const float xv = m[row * CM + tid];
        float a = xv, b = xv * xv;
#pragma unroll
        for (int o = 16; o > 0; o >>= 1) {
            a += __shfl_xor_sync(0xffffffffu, a, o);
            b += __shfl_xor_sync(0xffffffffu, b, o);
        }
        if ((tid & 31) == 0) { scr[tid >> 5] = a; scr[8 + (tid >> 5)] = b; }
        __syncthreads();
        if (tid < 32) {
            float x = (tid < 8) ? scr[tid] : 0.f;
            float y = (tid < 8) ? scr[8 + tid] : 0.f;
#pragma unroll
            for (int o = 4; o > 0; o >>= 1) {
                x += __shfl_xor_sync(0xffffffffu, x, o);
                y += __shfl_xor_sync(0xffffffffu, y, o);
            }
            if (tid == 0) { scr[0] = x; scr[8] = y; }
        }
        __syncthreads();
        const float mean = scr[0] * (1.f / 256.f);
        const float msq  = scr[8] * (1.f / 256.f);
        __syncthreads();
        const float var = msq - mean * mean;

        xs[tid] = (xv - mean) * rsqrtf(var + 1e-5f) * gam + bet;
        __syncthreads();

        float s = 0.f;
#pragma unroll
        for (int kk = 0; kk < 64; kk++) {
            const int k = part * 64 + kk;
            s += xs[k] * W[k * 32 + h];
        }
        sred[tid] = s;
        __syncthreads();

        if (tid < 64) {
            float tot = sred[tid] + sred[tid + 64] + sred[tid + 128] + sred[tid + 192];
            const float mk = mask[row];
            const int sidx = (i_loc * 32 + h) * 16 + n_loc;
            __nv_bfloat16 hi, lo;
            if (tid < 32) {
                split1((tot + ba[h]) * mk, hi, lo);
                sStage[0 * 1024 + sidx] = hi;
                sStage[1 * 1024 + sidx] = lo;
            } else {
                split1((tot + bb[h]) * mk, hi, lo);
                sStage[2 * 1024 + sidx] = hi;
                sStage[3 * 1024 + sidx] = lo;
            }
        }
        __syncthreads();
    }

#pragma unroll
    for (int v = 0; v < 2; v++) {
        const int fidx = v * 256 + tid;
        const int arr  = fidx >> 7;
        const int rem  = fidx & 127;
        const int il   = rem >> 6;
        const int hh   = (rem >> 1) & 31;
        const int half = rem & 1;
        const uint4 val = *reinterpret_cast<const uint4*>(
            sStage + arr * 1024 + (il * 32 + hh) * 16 + half * 8);
        __nv_bfloat16* gdst = (arr == 0) ? g_Ah : (arr == 1) ? g_Al : (arr == 2) ? g_Bh : g_Bl;
        reinterpret_cast<uint4*>(gdst)[((i0 + il) * 32 + hh) * 16 + nb * 2 + half] = val;
    }
}

// ---------------------------------------------------------------------------
// Prep: pair mask table + Wo^T bf16 split
// ---------------------------------------------------------------------------
__global__ __launch_bounds__(256) void prep_kernel(
    const float* __restrict__ mask, const float* __restrict__ Wo)
{
    if (blockIdx.x < 256) {
        const int i = blockIdx.x, j = threadIdx.x;
        float s = 0.f;
        for (int n = 0; n < NN; n++) s += mask[n * LL + i] * mask[n * LL + j];
        g_pm[i * LL + j] = s;
    } else {
        const int b = blockIdx.x - 256;
#pragma unroll
        for (int v = 0; v < 8; v++) {
            const int e = b * 2048 + v * 256 + threadIdx.x;
            const float val = Wo[e];
            const int k = e >> 7, z = e & 127;
            __nv_bfloat16 hi, lo;
            split1(val, hi, lo);
            g_Woh[z * 1024 + k] = hi;
            g_Wol[z * 1024 + k] = lo;
        }
    }
}

// ---------------------------------------------------------------------------
// mma1: O[8192,8192] = A^T B (K=128), bf16-split 3-product mma.sync
// CTA 128x128, 512 threads (4x4 warps, warp tile 32x32), full K in SMEM.
// SMEM rows padded to 272B (ldmatrix conflict-free: 272 mod 128 = 16).
// ---------------------------------------------------------------------------
#define S1_AH 0
#define S1_AL 34816
#define S1_BH 69632
#define S1_BL 104448
#define S1_SMEM 139264

__global__ __launch_bounds__(512) void mma1_kernel()
{
    extern __shared__ char smem[];
    const int tid = threadIdx.x;
    const int bm = blockIdx.y, bn = blockIdx.x;

#pragma unroll
    for (int v = 0; v < 16; v++) {
        const int idx = v * 512 + tid;
        const int buf = idx >> 11;
        const int rem = idx & 2047;
        const int row = rem >> 4, q = rem & 15;
        const int grow = ((buf < 2) ? bm : bn) * 128 + row;
        const __nv_bfloat16* src = (buf == 0) ? g_Ah : (buf == 1) ? g_Al
                                 : (buf == 2) ? g_Bh : g_Bl;
        const uint4 val = reinterpret_cast<const uint4*>(src)[grow * 16 + q];
        *reinterpret_cast<uint4*>(smem + buf * 34816 + row * 272 + q * 16) = val;
    }
    __syncthreads();

    const int lane = tid & 31;
    const int wid  = tid >> 5;
    const int wm = wid >> 2, wn = wid & 3;
    const uint32_t sb = smem_u32(smem);

    float acc[2][4][4];
#pragma unroll
    for (int fm = 0; fm < 2; fm++)
#pragma unroll
        for (int fn = 0; fn < 4; fn++)
#pragma unroll
            for (int e = 0; e < 4; e++) acc[fm][fn][e] = 0.f;

    const uint32_t rofs = (uint32_t)((lane & 15) * 272 + (lane >> 4) * 16);
    const uint32_t aAh = sb + S1_AH + wm * 32 * 272 + rofs;
    const uint32_t aAl = sb + S1_AL + wm * 32 * 272 + rofs;
    const uint32_t aBh = sb + S1_BH + wn * 32 * 272 + rofs;
    const uint32_t aBl = sb + S1_BL + wn * 32 * 272 + rofs;

#pragma unroll
    for (int ks = 0; ks < 8; ks++) {
        uint32_t A_h[2][4], A_l[2][4], B_h[2][4], B_l[2][4];
        ldsm4(A_h[0], aAh + ks * 32);
        ldsm4(A_h[1], aAh + 16 * 272 + ks * 32);
        ldsm4(A_l[0], aAl + ks * 32);
        ldsm4(A_l[1], aAl + 16 * 272 + ks * 32);
        ldsm4(B_h[0], aBh + ks * 32);
        ldsm4(B_h[1], aBh + 16 * 272 + ks * 32);
        ldsm4(B_l[0], aBl + ks * 32);
        ldsm4(B_l[1], aBl + 16 * 272 + ks * 32);
#pragma unroll
        for (int fm = 0; fm < 2; fm++)
#pragma unroll
            for (int fn = 0; fn < 4; fn++) {
                const uint32_t bh0 = B_h[fn >> 1][fn & 1];
                const uint32_t bh1 = B_h[fn >> 1][(fn & 1) + 2];
                const uint32_t bl0 = B_l[fn >> 1][fn & 1];
                const uint32_t bl1 = B_l[fn >> 1][(fn & 1) + 2];
                mma_bf16(acc[fm][fn], A_h[fm], bh0, bh1);
                mma_bf16(acc[fm][fn], A_h[fm], bl0, bl1);
                mma_bf16(acc[fm][fn], A_l[fm], bh0, bh1);
            }
    }

    const int r0 = bm * 128 + wm * 32 + (lane >> 2);
    const int c0 = bn * 128 + wn * 32 + (lane & 3) * 2;
#pragma unroll
    for (int fm = 0; fm < 2; fm++)
#pragma unroll
        for (int fn = 0; fn < 4; fn++) {
            float2 v0 = make_float2(acc[fm][fn][0], acc[fm][fn][1]);
            float2 v1 = make_float2(acc[fm][fn][2], acc[fm][fn][3]);
            *reinterpret_cast<float2*>(g_O + (size_t)(r0 + fm * 16) * RTOT + c0 + fn * 8) = v0;
            *reinterpret_cast<float2*>(g_O + (size_t)(r0 + fm * 16 + 8) * RTOT + c0 + fn * 8) = v1;
        }
}

// ---------------------------------------------------------------------------
// mma2: Z = O2 @ Wo^T.  CTA: i fixed, 128 j pairs (M=128), N=128, K=1024.
// O2[p=jl][k=c*32+d] = g_O[i*32+c][(j0+jl)*32+d], fp32 -> bf16 split on load.
// SMEM rows padded to 144B.
// ---------------------------------------------------------------------------
#define S2_AH 0
#define S2_AL 18432
#define S2_BH 36864
#define S2_BL 55296
#define S2_SMEM 73728

__global__ __launch_bounds__(512) void mma2_kernel(
    const float* __restrict__ bo, float* __restrict__ out)
{
    extern __shared__ char smem[];
    const int tid = threadIdx.x;
    const int i  = blockIdx.x >> 1;
    const int j0 = (blockIdx.x & 1) * 128;

    const int lane = tid & 31;
    const int wid  = tid >> 5;
    const int wm = wid >> 2, wn = wid & 3;
    const uint32_t sb = smem_u32(smem);

    float acc[2][4][4];
#pragma unroll
    for (int fm = 0; fm < 2; fm++)
#pragma unroll
        for (int fn = 0; fn < 4; fn++)
#pragma unroll
            for (int e = 0; e < 4; e++) acc[fm][fn][e] = 0.f;

    const uint32_t rofs = (uint32_t)((lane & 15) * 144 + (lane >> 4) * 16);
    const uint32_t aAh = sb + S2_AH + wm * 32 * 144 + rofs;
    const uint32_t aAl = sb + S2_AL + wm * 32 * 144 + rofs;
    const uint32_t aBh = sb + S2_BH + wn * 32 * 144 + rofs;
    const uint32_t aBl = sb + S2_BL + wn * 32 * 144 + rofs;

    for (int ck = 0; ck < 16; ck++) {
        float4 ro[4];
        uint4 rw[4];
#pragma unroll
        for (int v = 0; v < 4; v++) {
            const int f4 = v * 512 + tid;
            const int jl = f4 >> 4, q = f4 & 15;
            const int cc = q >> 3, d4 = q & 7;
            ro[v] = *reinterpret_cast<const float4*>(
                g_O + (size_t)(i * 32 + ck * 2 + cc) * RTOT + (j0 + jl) * 32 + d4 * 4);
        }
#pragma unroll
        for (int v = 0; v < 4; v++) {
            const int idx = v * 512 + tid;
            const int buf = idx >> 10;
            const int rem = idx & 1023;
            const int z = rem >> 3, q = rem & 7;
            const __nv_bfloat16* src = buf ? g_Wol : g_Woh;
            rw[v] = reinterpret_cast<const uint4*>(src)[z * 128 + ck * 8 + q];
        }

        __syncthreads();   // previous chunk's compute done before overwrite

#pragma unroll
        for (int v = 0; v < 4; v++) {
            const int f4 = v * 512 + tid;
            const int jl = f4 >> 4, q = f4 & 15;
            const int cc = q >> 3, d4 = q & 7;
            __nv_bfloat162 h01, h23, l01, l23;
            split1(ro[v].x, h01.x, l01.x);
            split1(ro[v].y, h01.y, l01.y);
            split1(ro[v].z, h23.x, l23.x);
            split1(ro[v].w, h23.y, l23.y);
            uint2 hv, lv;
            hv.x = *reinterpret_cast<uint32_t*>(&h01);
            hv.y = *reinterpret_cast<uint32_t*>(&h23);
            lv.x = *reinterpret_cast<uint32_t*>(&l01);
            lv.y = *reinterpret_cast<uint32_t*>(&l23);
            const uint32_t off = (uint32_t)(jl * 144 + (cc * 32 + d4 * 4) * 2);
            *reinterpret_cast<uint2*>(smem + S2_AH + off) = hv;
            *reinterpret_cast<uint2*>(smem + S2_AL + off) = lv;
        }
#pragma unroll
        for (int v = 0; v < 4; v++) {
            const int idx = v * 512 + tid;
            const int buf = idx >> 10;
            const int rem = idx & 1023;
            const int z = rem >> 3, q = rem & 7;
            *reinterpret_cast<uint4*>(smem + S2_BH + buf * 18432 + z * 144 + q * 16) = rw[v];
        }
        __syncthreads();

#pragma unroll
        for (int ks = 0; ks < 4; ks++) {
            uint32_t A_h[2][4], A_l[2][4], B_h[2][4], B_l[2][4];
            ldsm4(A_h[0], aAh + ks * 32);
            ldsm4(A_h[1], aAh + 16 * 144 + ks * 32);
            ldsm4(A_l[0], aAl + ks * 32);
            ldsm4(A_l[1], aAl + 16 * 144 + ks * 32);
            ldsm4(B_h[0], aBh + ks * 32);
            ldsm4(B_h[1], aBh + 16 * 144 + ks * 32);
            ldsm4(B_l[0], aBl + ks * 32);
            ldsm4(B_l[1], aBl + 16 * 144 + ks * 32);
#pragma unroll
            for (int fm = 0; fm < 2; fm++)
#pragma unroll
                for (int fn = 0; fn < 4; fn++) {
                    const uint32_t bh0 = B_h[fn >> 1][fn & 1];
                    const uint32_t bh1 = B_h[fn >> 1][(fn & 1) + 2];
                    const uint32_t bl0 = B_l[fn >> 1][fn & 1];
                    const uint32_t bl1 = B_l[fn >> 1][(fn & 1) + 2];
                    mma_bf16(acc[fm][fn], A_h[fm], bh0, bh1);
                    mma_bf16(acc[fm][fn], A_h[fm], bl0, bl1);
                    mma_bf16(acc[fm][fn], A_l[fm], bh0, bh1);
                }
        }
    }

    const int jl0 = wm * 32 + (lane >> 2);
    const int z0  = wn * 32 + (lane & 3) * 2;
#pragma unroll
    for (int fm = 0; fm < 2; fm++) {
#pragma unroll
        for (int half = 0; half < 2; half++) {
            const int jl = jl0 + fm * 16 + half * 8;
            const int j = j0 + jl;
            const float inv = 1.f / (g_pm[i * LL + j] + 1e-8f);
#pragma unroll
            for (int fn = 0; fn < 4; fn++) {
                const int z = z0 + fn * 8;
                float2 res;
                res.x = acc[fm][fn][half * 2 + 0] * inv + bo[z];
                res.y = acc[fm][fn][half * 2 + 1] * inv + bo[z + 1];
                *reinterpret_cast<float2*>(out + (size_t)(i * LL + j) * CZ + z) = res;
            }
        }
    }
}

// ---------------------------------------------------------------------------
extern "C" void kernel_launch(void* const* d_in, const int* in_sizes, int n_in,
                              void* d_out, int out_size)
{
    const float* m     = (const float*)d_in[0];
    const float* mask  = (const float*)d_in[1];
    const float* gamma = (const float*)d_in[2];
    const float* beta  = (const float*)d_in[3];
    const float* Wa    = (const float*)d_in[4];
    const float* ba    = (const float*)d_in[5];
    const float* Wb    = (const float*)d_in[6];
    const float* bb    = (const float*)d_in[7];
    const float* Wo    = (const float*)d_in[8];
    const float* bo    = (const float*)d_in[9];
    float* out = (float*)d_out;

    const int smem1 = 16912 * 4 + 4096 * 2;
    cudaFuncSetAttribute(ln_proj_kernel, cudaFuncAttributeMaxDynamicSharedMemorySize, smem1);
    cudaFuncSetAttribute(mma1_kernel,    cudaFuncAttributeMaxDynamicSharedMemorySize, S1_SMEM);
    cudaFuncSetAttribute(mma2_kernel,    cudaFuncAttributeMaxDynamicSharedMemorySize, S2_SMEM);

    ln_proj_kernel<<<1024, 256, smem1>>>(m, mask, gamma, beta, Wa, ba, Wb, bb);
    prep_kernel<<<320, 256>>>(mask, Wo);
    mma1_kernel<<<dim3(64, 64), 512, S1_SMEM>>>();
    mma2_kernel<<<512, 512, S2_SMEM>>>(bo, out);
}

// round 6
// speedup vs baseline: 3.0930x; 1.0273x over previous
#include <cuda_runtime.h>
#include <cuda_bf16.h>
#include <cstdint>

#define NN 128
#define LL 256
#define CM 256
#define CH 32
#define CZ 128
#define RTOT 8192   // LL*CH

// ---------------- global scratch ----------------
__device__ __align__(16) __nv_bfloat16 g_Ah[RTOT * NN];   // [r][n] K-major, ld=128
__device__ __align__(16) __nv_bfloat16 g_Al[RTOT * NN];
__device__ __align__(16) __nv_bfloat16 g_Bh[RTOT * NN];
__device__ __align__(16) __nv_bfloat16 g_Bl[RTOT * NN];
__device__ __align__(16) __nv_bfloat16 g_Woh[CZ * 1024];  // [z][k] (Wo^T)
__device__ __align__(16) __nv_bfloat16 g_Wol[CZ * 1024];
__device__ float g_pm[LL * LL];
// O in bf16 hi/lo, layout [pair = i*256+j][k = c*32+d]  (stage-2 A operand)
__device__ __align__(16) __nv_bfloat16 g_Oh[(size_t)65536 * 1024];   // 128 MB
__device__ __align__(16) __nv_bfloat16 g_Ol[(size_t)65536 * 1024];   // 128 MB

// ---------------- helpers ----------------
__device__ __forceinline__ uint32_t smem_u32(const void* p) {
    uint32_t a;
    asm("{ .reg .u64 t; cvta.to.shared.u64 t, %1; cvt.u32.u64 %0, t; }" : "=r"(a) : "l"(p));
    return a;
}
__device__ __forceinline__ void ldsm4(uint32_t* r, uint32_t addr) {
    asm volatile("ldmatrix.sync.aligned.m8n8.x4.shared.b16 {%0,%1,%2,%3}, [%4];"
        : "=r"(r[0]), "=r"(r[1]), "=r"(r[2]), "=r"(r[3]) : "r"(addr));
}
__device__ __forceinline__ void mma_bf16(float* d, const uint32_t* a,
                                         uint32_t b0, uint32_t b1) {
    asm volatile(
        "mma.sync.aligned.m16n8k16.row.col.f32.bf16.bf16.f32 "
        "{%0,%1,%2,%3}, {%4,%5,%6,%7}, {%8,%9}, {%0,%1,%2,%3};"
        : "+f"(d[0]), "+f"(d[1]), "+f"(d[2]), "+f"(d[3])
        : "r"(a[0]), "r"(a[1]), "r"(a[2]), "r"(a[3]), "r"(b0), "r"(b1));
}
#define CP16(dst, src) asm volatile("cp.async.cg.shared.global [%0], [%1], 16;" :: "r"(dst), "l"(src))
#define CP_COMMIT()    asm volatile("cp.async.commit_group;" ::: "memory")
#define CP_WAIT(n)     asm volatile("cp.async.wait_group %0;" :: "n"(n) : "memory")

__device__ __forceinline__ void split1(float x, __nv_bfloat16& h, __nv_bfloat16& l) {
    h = __float2bfloat16(x);
    l = __float2bfloat16(x - __bfloat162float(h));
}

// ---------------------------------------------------------------------------
// Kernel 1: LayerNorm + projections -> bf16 hi/lo, layout [i*32+h][n]
// ---------------------------------------------------------------------------
__global__ __launch_bounds__(256) void ln_proj_kernel(
    const float* __restrict__ m, const float* __restrict__ mask,
    const float* __restrict__ gamma, const float* __restrict__ beta,
    const float* __restrict__ Wa, const float* __restrict__ ba,
    const float* __restrict__ Wb, const float* __restrict__ bb)
{
    extern __shared__ float sm1[];
    float* sWa  = sm1;
    float* sWb  = sWa + 8192;
    float* xs   = sWb + 8192;
    float* sred = xs + 256;
    float* scr  = sred + 256;
    __nv_bfloat16* sStage = (__nv_bfloat16*)(scr + 16);

    const int tid = threadIdx.x;
    for (int l = tid; l < 8192; l += 256) { sWa[l] = Wa[l]; sWb[l] = Wb[l]; }
    __syncthreads();

    const float gam = gamma[tid];
    const float bet = beta[tid];

    const int outp = tid & 63;
    const int part = tid >> 6;
    const int h    = outp & 31;
    const float* W = (outp < 32) ? sWa : sWb;

    const int nb = blockIdx.x >> 7;
    const int ib = blockIdx.x & 127;
    const int n0 = nb * 16;
    const int i0 = ib * 2;

    for (int rr = 0; rr < 32; rr++) {
        const int n_loc = rr & 15;
        const int i_loc = rr >> 4;
        const int row = (n0 + n_loc) * LL + (i0 + i_loc);

        const float xv = m[row * CM + tid];
        float a = xv, b = xv * xv;
#pragma unroll
        for (int o = 16; o > 0; o >>= 1) {
            a += __shfl_xor_sync(0xffffffffu, a, o);
            b += __shfl_xor_sync(0xffffffffu, b, o);
        }
        if ((tid & 31) == 0) { scr[tid >> 5] = a; scr[8 + (tid >> 5)] = b; }
        __syncthreads();
        if (tid < 32) {
            float x = (tid < 8) ? scr[tid] : 0.f;
            float y = (tid < 8) ? scr[8 + tid] : 0.f;
#pragma unroll
            for (int o = 4; o > 0; o >>= 1) {
                x += __shfl_xor_sync(0xffffffffu, x, o);
                y += __shfl_xor_sync(0xffffffffu, y, o);
            }
            if (tid == 0) { scr[0] = x; scr[8] = y; }
        }
        __syncthreads();
        const float mean = scr[0] * (1.f / 256.f);
        const float msq  = scr[8] * (1.f / 256.f);
        __syncthreads();
        const float var = msq - mean * mean;

        xs[tid] = (xv - mean) * rsqrtf(var + 1e-5f) * gam + bet;
        __syncthreads();

        float s = 0.f;
#pragma unroll
        for (int kk = 0; kk < 64; kk++) {
            const int k = part * 64 + kk;
            s += xs[k] * W[k * 32 + h];
        }
        sred[tid] = s;
        __syncthreads();

        if (tid < 64) {
            float tot = sred[tid] + sred[tid + 64] + sred[tid + 128] + sred[tid + 192];
            const float mk = mask[row];
            const int sidx = (i_loc * 32 + h) * 16 + n_loc;
            __nv_bfloat16 hi, lo;
            if (tid < 32) {
                split1((tot + ba[h]) * mk, hi, lo);
                sStage[0 * 1024 + sidx] = hi;
                sStage[1 * 1024 + sidx] = lo;
            } else {
                split1((tot + bb[h]) * mk, hi, lo);
                sStage[2 * 1024 + sidx] = hi;
                sStage[3 * 1024 + sidx] = lo;
            }
        }
        __syncthreads();
    }

#pragma unroll
    for (int v = 0; v < 2; v++) {
        const int fidx = v * 256 + tid;
        const int arr  = fidx >> 7;
        const int rem  = fidx & 127;
        const int il   = rem >> 6;
        const int hh   = (rem >> 1) & 31;
        const int half = rem & 1;
        const uint4 val = *reinterpret_cast<const uint4*>(
            sStage + arr * 1024 + (il * 32 + hh) * 16 + half * 8);
        __nv_bfloat16* gdst = (arr == 0) ? g_Ah : (arr == 1) ? g_Al : (arr == 2) ? g_Bh : g_Bl;
        reinterpret_cast<uint4*>(gdst)[((i0 + il) * 32 + hh) * 16 + nb * 2 + half] = val;
    }
}

// ---------------------------------------------------------------------------
// Prep: pair mask table + Wo^T bf16 split
// ---------------------------------------------------------------------------
__global__ __launch_bounds__(256) void prep_kernel(
    const float* __restrict__ mask, const float* __restrict__ Wo)
{
    if (blockIdx.x < 256) {
        const int i = blockIdx.x, j = threadIdx.x;
        float s = 0.f;
        for (int n = 0; n < NN; n++) s += mask[n * LL + i] * mask[n * LL + j];
        g_pm[i * LL + j] = s;
    } else {
        const int b = blockIdx.x - 256;
#pragma unroll
        for (int v = 0; v < 8; v++) {
            const int e = b * 2048 + v * 256 + threadIdx.x;
            const float val = Wo[e];
            const int k = e >> 7, z = e & 127;
            __nv_bfloat16 hi, lo;
            split1(val, hi, lo);
            g_Woh[z * 1024 + k] = hi;
            g_Wol[z * 1024 + k] = lo;
        }
    }
}

// ---------------------------------------------------------------------------
// mma1: O = A^T B (tile 128x128, K=128), cp.async split-K pipeline.
// Epilogue: bf16 hi/lo split, store to g_Oh/g_Ol in [pair][k] layout.
// SMEM: 4 bufs x (128 rows x 272 B)  (256 data + 16 pad)
// ---------------------------------------------------------------------------
#define S1_BUF 34816
#define S1_SMEM 139264

__global__ __launch_bounds__(512) void mma1_kernel()
{
    extern __shared__ char smem[];
    const uint32_t sb = smem_u32(smem);
    const int tid = threadIdx.x;
    const int bm = blockIdx.y, bn = blockIdx.x;

    // issue both k-halves as separate cp.async groups
#pragma unroll
    for (int kh = 0; kh < 2; kh++) {
#pragma unroll
        for (int v = 0; v < 8; v++) {
            const int idx = v * 512 + tid;          // 0..4095
            const int buf = idx >> 10;
            const int rem = idx & 1023;
            const int row = rem >> 3, q = rem & 7;
            const int grow = ((buf < 2) ? bm : bn) * 128 + row;
            const __nv_bfloat16* src = (buf == 0) ? g_Ah : (buf == 1) ? g_Al
                                     : (buf == 2) ? g_Bh : g_Bl;
            CP16(sb + buf * S1_BUF + row * 272 + kh * 128 + q * 16,
                 src + (size_t)grow * 128 + kh * 64 + q * 8);
        }
        CP_COMMIT();
    }

    const int lane = tid & 31;
    const int wid  = tid >> 5;
    const int wm = wid >> 2, wn = wid & 3;

    float acc[2][4][4];
#pragma unroll
    for (int fm = 0; fm < 2; fm++)
#pragma unroll
        for (int fn = 0; fn < 4; fn++)
#pragma unroll
            for (int e = 0; e < 4; e++) acc[fm][fn][e] = 0.f;

    const uint32_t rofs = (uint32_t)((lane & 15) * 272 + (lane >> 4) * 16);
    const uint32_t aAh = sb + 0 * S1_BUF + wm * 32 * 272 + rofs;
    const uint32_t aAl = sb + 1 * S1_BUF + wm * 32 * 272 + rofs;
    const uint32_t aBh = sb + 2 * S1_BUF + wn * 32 * 272 + rofs;
    const uint32_t aBl = sb + 3 * S1_BUF + wn * 32 * 272 + rofs;

    CP_WAIT(1);
    __syncthreads();

#pragma unroll
    for (int ks = 0; ks < 8; ks++) {
        if (ks == 4) { CP_WAIT(0); __syncthreads(); }
        uint32_t A_h[2][4], A_l[2][4], B_h[2][4], B_l[2][4];
        ldsm4(A_h[0], aAh + ks * 32);
        ldsm4(A_h[1], aAh + 16 * 272 + ks * 32);
        ldsm4(A_l[0], aAl + ks * 32);
        ldsm4(A_l[1], aAl + 16 * 272 + ks * 32);
        ldsm4(B_h[0], aBh + ks * 32);
        ldsm4(B_h[1], aBh + 16 * 272 + ks * 32);
        ldsm4(B_l[0], aBl + ks * 32);
        ldsm4(B_l[1], aBl + 16 * 272 + ks * 32);
#pragma unroll
        for (int fm = 0; fm < 2; fm++)
#pragma unroll
            for (int fn = 0; fn < 4; fn++) {
                const uint32_t bh0 = B_h[fn >> 1][fn & 1];
                const uint32_t bh1 = B_h[fn >> 1][(fn & 1) + 2];
                const uint32_t bl0 = B_l[fn >> 1][fn & 1];
                const uint32_t bl1 = B_l[fn >> 1][(fn & 1) + 2];
                mma_bf16(acc[fm][fn], A_h[fm], bh0, bh1);
                mma_bf16(acc[fm][fn], A_h[fm], bl0, bl1);
                mma_bf16(acc[fm][fn], A_l[fm], bh0, bh1);
            }
    }

    // epilogue: warp (wm,wn) owns pair (i = bm*4+wm, j = bn*4+wn)
    const int i_g = bm * 4 + wm, j_g = bn * 4 + wn;
    __nv_bfloat16* oh = g_Oh + (size_t)(i_g * 256 + j_g) * 1024;
    __nv_bfloat16* ol = g_Ol + (size_t)(i_g * 256 + j_g) * 1024;
#pragma unroll
    for (int fm = 0; fm < 2; fm++)
#pragma unroll
        for (int fn = 0; fn < 4; fn++)
#pragma unroll
            for (int half = 0; half < 2; half++) {
                const int c = (lane >> 2) + half * 8 + fm * 16;
                const int k = c * 32 + (lane & 3) * 2 + fn * 8;
                __nv_bfloat162 h2, l2;
                split1(acc[fm][fn][half * 2 + 0], h2.x, l2.x);
                split1(acc[fm][fn][half * 2 + 1], h2.y, l2.y);
                *reinterpret_cast<__nv_bfloat162*>(oh + k) = h2;
                *reinterpret_cast<__nv_bfloat162*>(ol + k) = l2;
            }
}

// ---------------------------------------------------------------------------
// mma2: Z = O @ Wo^T.  CTA: M=128 pairs, N=128, K=1024, cp.async double buffer.
// SMEM per stage: 4 bufs x (128 rows x 144 B), 2 stages.
// ---------------------------------------------------------------------------
#define S2_BUF 18432
#define S2_STAGE 73728
#define S2_SMEM 147456

__device__ __forceinline__ void mma2_load_chunk(uint32_t sb, int st, int ck,
                                                int tid, size_t pairbase)
{
#pragma unroll
    for (int v = 0; v < 8; v++) {
        const int idx = v * 512 + tid;       // 0..4095
        const int buf = idx >> 10;
        const int rem = idx & 1023;
        const int row = rem >> 3, q = rem & 7;
        const __nv_bfloat16* src;
        if (buf == 0)      src = g_Oh + (pairbase + row) * 1024 + ck * 64 + q * 8;
        else if (buf == 1) src = g_Ol + (pairbase + row) * 1024 + ck * 64 + q * 8;
        else if (buf == 2) src = g_Woh + (size_t)row * 1024 + ck * 64 + q * 8;
        else               src = g_Wol + (size_t)row * 1024 + ck * 64 + q * 8;
        CP16(sb + st * S2_STAGE + buf * S2_BUF + row * 144 + q * 16, src);
    }
    CP_COMMIT();
}

__global__ __launch_bounds__(512) void mma2_kernel(
    const float* __restrict__ bo, float* __restrict__ out)
{
    extern __shared__ char smem[];
    const uint32_t sb = smem_u32(smem);
    const int tid = threadIdx.x;
    const int i  = blockIdx.x >> 1;
    const int j0 = (blockIdx.x & 1) * 128;
    const size_t pairbase = (size_t)i * 256 + j0;

    const int lane = tid & 31;
    const int wid  = tid >> 5;
    const int wm = wid >> 2, wn = wid & 3;

    float acc[2][4][4];
#pragma unroll
    for (int fm = 0; fm < 2; fm++)
#pragma unroll
        for (int fn = 0; fn < 4; fn++)
#pragma unroll
            for (int e = 0; e < 4; e++) acc[fm][fn][e] = 0.f;

    const uint32_t rofs = (uint32_t)((lane & 15) * 144 + (lane >> 4) * 16);

    mma2_load_chunk(sb, 0, 0, tid, pairbase);

    for (int ck = 0; ck < 16; ck++) {
        const int st = ck & 1;
        if (ck < 15) {
            mma2_load_chunk(sb, st ^ 1, ck + 1, tid, pairbase);
            CP_WAIT(1);
        } else {
            CP_WAIT(0);
        }
        __syncthreads();

        const uint32_t base = sb + st * S2_STAGE;
        const uint32_t aAh = base + 0 * S2_BUF + wm * 32 * 144 + rofs;
        const uint32_t aAl = base + 1 * S2_BUF + wm * 32 * 144 + rofs;
        const uint32_t aBh = base + 2 * S2_BUF + wn * 32 * 144 + rofs;
        const uint32_t aBl = base + 3 * S2_BUF + wn * 32 * 144 + rofs;

#pragma unroll
        for (int ks = 0; ks < 4; ks++) {
            uint32_t A_h[2][4], A_l[2][4], B_h[2][4], B_l[2][4];
            ldsm4(A_h[0], aAh + ks * 32);
            ldsm4(A_h[1], aAh + 16 * 144 + ks * 32);
            ldsm4(A_l[0], aAl + ks * 32);
            ldsm4(A_l[1], aAl + 16 * 144 + ks * 32);
            ldsm4(B_h[0], aBh + ks * 32);
            ldsm4(B_h[1], aBh + 16 * 144 + ks * 32);
            ldsm4(B_l[0], aBl + ks * 32);
            ldsm4(B_l[1], aBl + 16 * 144 + ks * 32);
#pragma unroll
            for (int fm = 0; fm < 2; fm++)
#pragma unroll
                for (int fn = 0; fn < 4; fn++) {
                    const uint32_t bh0 = B_h[fn >> 1][fn & 1];
                    const uint32_t bh1 = B_h[fn >> 1][(fn & 1) + 2];
                    const uint32_t bl0 = B_l[fn >> 1][fn & 1];
                    const uint32_t bl1 = B_l[fn >> 1][(fn & 1) + 2];
                    mma_bf16(acc[fm][fn], A_h[fm], bh0, bh1);
                    mma_bf16(acc[fm][fn], A_h[fm], bl0, bl1);
                    mma_bf16(acc[fm][fn], A_l[fm], bh0, bh1);
                }
        }
        __syncthreads();   // all reads of this stage done before it's reloaded
    }

    const int jl0 = wm * 32 + (lane >> 2);
    const int z0  = wn * 32 + (lane & 3) * 2;
#pragma unroll
    for (int fm = 0; fm < 2; fm++) {
#pragma unroll
        for (int half = 0; half < 2; half++) {
            const int jl = jl0 + fm * 16 + half * 8;
            const int j = j0 + jl;
            const float inv = 1.f / (g_pm[i * LL + j] + 1e-8f);
#pragma unroll
            for (int fn = 0; fn < 4; fn++) {
                const int z = z0 + fn * 8;
                float2 res;
                res.x = acc[fm][fn][half * 2 + 0] * inv + bo[z];
                res.y = acc[fm][fn][half * 2 + 1] * inv + bo[z + 1];
                *reinterpret_cast<float2*>(out + (size_t)(i * LL + j) * CZ + z) = res;
            }
        }
    }
}

// ---------------------------------------------------------------------------
extern "C" void kernel_launch(void* const* d_in, const int* in_sizes, int n_in,
                              void* d_out, int out_size)
{
    const float* m     = (const float*)d_in[0];
    const float* mask  = (const float*)d_in[1];
    const float* gamma = (const float*)d_in[2];
    const float* beta  = (const float*)d_in[3];
    const float* Wa    = (const float*)d_in[4];
    const float* ba    = (const float*)d_in[5];
    const float* Wb    = (const float*)d_in[6];
    const float* bb    = (const float*)d_in[7];
    const float* Wo    = (const float*)d_in[8];
    const float* bo    = (const float*)d_in[9];
    float* out = (float*)d_out;

    const int smem1 = 16912 * 4 + 4096 * 2;
    cudaFuncSetAttribute(ln_proj_kernel, cudaFuncAttributeMaxDynamicSharedMemorySize, smem1);
    cudaFuncSetAttribute(mma1_kernel,    cudaFuncAttributeMaxDynamicSharedMemorySize, S1_SMEM);
    cudaFuncSetAttribute(mma2_kernel,    cudaFuncAttributeMaxDynamicSharedMemorySize, S2_SMEM);

    ln_proj_kernel<<<1024, 256, smem1>>>(m, mask, gamma, beta, Wa, ba, Wb, bb);
    prep_kernel<<<320, 256>>>(mask, Wo);
    mma1_kernel<<<dim3(64, 64), 512, S1_SMEM>>>();
    mma2_kernel<<<512, 512, S2_SMEM>>>(bo, out);
}